// round 1
// baseline (speedup 1.0000x reference)
#include <cuda_runtime.h>
#include <math.h>

#define BN 8192
#define CD 256
#define LITERS 100
#define SEG 32
#define SEGROWS (BN / SEG)   // 256 rows per segment
#define RPB 8                // rows per block in row-structured kernels
#define TB 128
#define TK 16

// ---- device scratch (no allocations allowed) ----
__device__ float g_K[67108864];          // 8192*8192 fp32 = 256 MB, K~ = 2*x*y^T
__device__ float g_a[BN];
__device__ float g_b[BN];
__device__ float g_pm[SEG * BN];         // partial lse max per (segment, col)
__device__ float g_ps[SEG * BN];         // partial lse sum per (segment, col)
__device__ unsigned int g_cnt[BN / 256]; // per-colblock completion counters (zero-init, self-resetting)

// ---- online logsumexp helpers ----
__device__ __forceinline__ void lse_upd(float& m, float& s, float v) {
    if (v > m) { s = s * __expf(m - v) + 1.0f; m = v; }
    else       { s += __expf(v - m); }
}
__device__ __forceinline__ void lse_mrg(float& m, float& s, float m2, float s2) {
    if (m2 > m) { s = s * __expf(m - m2) + s2; m = m2; }
    else        { s += s2 * __expf(m2 - m); }
}

// ---- b0 = -||y_j||^2 ----
__global__ void init_b_kernel(const float* __restrict__ Y) {
    int row  = blockIdx.x * blockDim.y + threadIdx.y;
    int lane = threadIdx.x;
    const float* yr = Y + (size_t)row * CD;
    float s = 0.f;
    #pragma unroll
    for (int c = lane; c < CD; c += 32) { float v = yr[c]; s += v * v; }
    #pragma unroll
    for (int o = 16; o; o >>= 1) s += __shfl_down_sync(0xffffffffu, s, o);
    if (lane == 0) g_b[row] = -s;
}

// ---- K~ = 2 * X * Y^T  (both row-major [BN, CD], TN gemm) ----
__global__ __launch_bounds__(256) void gemm_kernel(const float* __restrict__ X,
                                                   const float* __restrict__ Y) {
    __shared__ float As[TK][TB + 4];
    __shared__ float Bs[TK][TB + 4];
    int tid = threadIdx.x;
    int i0 = blockIdx.y * TB, j0 = blockIdx.x * TB;
    int tx = tid & 15, ty = tid >> 4;
    int lr = tid >> 2, lk = (tid & 3) << 2;

    float acc[8][8];
    #pragma unroll
    for (int r = 0; r < 8; r++)
        #pragma unroll
        for (int c = 0; c < 8; c++) acc[r][c] = 0.f;

    for (int k0 = 0; k0 < CD; k0 += TK) {
        float4 xa = *(const float4*)(X + (size_t)(i0 + lr) * CD + k0 + lk);
        float4 xb = *(const float4*)(X + (size_t)(i0 + lr + 64) * CD + k0 + lk);
        float4 ya = *(const float4*)(Y + (size_t)(j0 + lr) * CD + k0 + lk);
        float4 yb = *(const float4*)(Y + (size_t)(j0 + lr + 64) * CD + k0 + lk);
        __syncthreads();
        As[lk + 0][lr] = xa.x; As[lk + 1][lr] = xa.y; As[lk + 2][lr] = xa.z; As[lk + 3][lr] = xa.w;
        As[lk + 0][lr + 64] = xb.x; As[lk + 1][lr + 64] = xb.y; As[lk + 2][lr + 64] = xb.z; As[lk + 3][lr + 64] = xb.w;
        Bs[lk + 0][lr] = ya.x; Bs[lk + 1][lr] = ya.y; Bs[lk + 2][lr] = ya.z; Bs[lk + 3][lr] = ya.w;
        Bs[lk + 0][lr + 64] = yb.x; Bs[lk + 1][lr + 64] = yb.y; Bs[lk + 2][lr + 64] = yb.z; Bs[lk + 3][lr + 64] = yb.w;
        __syncthreads();
        #pragma unroll
        for (int kk = 0; kk < TK; kk++) {
            float4 a0 = *(const float4*)&As[kk][ty * 8];
            float4 a1 = *(const float4*)&As[kk][ty * 8 + 4];
            float4 b0 = *(const float4*)&Bs[kk][tx * 8];
            float4 b1 = *(const float4*)&Bs[kk][tx * 8 + 4];
            float ar[8] = {a0.x, a0.y, a0.z, a0.w, a1.x, a1.y, a1.z, a1.w};
            float br[8] = {b0.x, b0.y, b0.z, b0.w, b1.x, b1.y, b1.z, b1.w};
            #pragma unroll
            for (int r = 0; r < 8; r++)
                #pragma unroll
                for (int c = 0; c < 8; c++) acc[r][c] += ar[r] * br[c];
        }
    }
    #pragma unroll
    for (int r = 0; r < 8; r++) {
        float* orow = g_K + (size_t)(i0 + ty * 8 + r) * BN + j0 + tx * 8;
        float4 o0 = make_float4(2.f * acc[r][0], 2.f * acc[r][1], 2.f * acc[r][2], 2.f * acc[r][3]);
        float4 o1 = make_float4(2.f * acc[r][4], 2.f * acc[r][5], 2.f * acc[r][6], 2.f * acc[r][7]);
        *(float4*)orow       = o0;
        *(float4*)(orow + 4) = o1;
    }
}

// ---- a[i] = -lse_j(K~[i,j] + b[j]) : block owns RPB full rows ----
__global__ __launch_bounds__(256) void row_pass_kernel() {
    __shared__ float4 sb4[BN / 4];   // 32 KB: all of b
    __shared__ float rm[256];
    __shared__ float rs[256];
    int tid = threadIdx.x;
    const float4* b4 = (const float4*)g_b;
    for (int j = tid; j < BN / 4; j += 256) sb4[j] = b4[j];
    __syncthreads();

    for (int r = 0; r < RPB; r++) {
        int row = blockIdx.x * RPB + r;
        const float4* rp = (const float4*)(g_K + (size_t)row * BN);
        float m0 = -INFINITY, s0 = 0.f, m1 = -INFINITY, s1 = 0.f;
        float m2 = -INFINITY, s2 = 0.f, m3 = -INFINITY, s3 = 0.f;
        #pragma unroll
        for (int it = 0; it < (BN / 4) / 256; it++) {
            int jj = tid + it * 256;
            float4 v = rp[jj];
            float4 bb = sb4[jj];
            lse_upd(m0, s0, v.x + bb.x);
            lse_upd(m1, s1, v.y + bb.y);
            lse_upd(m2, s2, v.z + bb.z);
            lse_upd(m3, s3, v.w + bb.w);
        }
        lse_mrg(m0, s0, m1, s1);
        lse_mrg(m2, s2, m3, s3);
        lse_mrg(m0, s0, m2, s2);
        rm[tid] = m0; rs[tid] = s0;
        __syncthreads();
        for (int off = 128; off; off >>= 1) {
            if (tid < off) {
                float mm = rm[tid], ss = rs[tid];
                lse_mrg(mm, ss, rm[tid + off], rs[tid + off]);
                rm[tid] = mm; rs[tid] = ss;
            }
            __syncthreads();
        }
        if (tid == 0) g_a[row] = -(rm[0] + logf(rs[0]));
        __syncthreads();
    }
}

// ---- b[j] = -lse_i(K~[i,j] + a[i]) : segmented partials + last-block combine ----
__global__ __launch_bounds__(256) void col_pass_kernel() {
    __shared__ float sa[SEGROWS];
    __shared__ int lastf;
    int cb = blockIdx.x;   // column block 0..31
    int seg = blockIdx.y;  // row segment 0..SEG-1
    int tid = threadIdx.x;
    int j = cb * 256 + tid;
    for (int i = tid; i < SEGROWS; i += 256) sa[i] = g_a[seg * SEGROWS + i];
    __syncthreads();

    float m0 = -INFINITY, s0 = 0.f, m1 = -INFINITY, s1 = 0.f;
    float m2 = -INFINITY, s2 = 0.f, m3 = -INFINITY, s3 = 0.f;
    const float* p = g_K + (size_t)seg * SEGROWS * BN + j;
    #pragma unroll 2
    for (int i = 0; i < SEGROWS; i += 4) {
        float v0 = p[0]      + sa[i];
        float v1 = p[BN]     + sa[i + 1];
        float v2 = p[2 * BN] + sa[i + 2];
        float v3 = p[3 * BN] + sa[i + 3];
        p += 4 * BN;
        lse_upd(m0, s0, v0);
        lse_upd(m1, s1, v1);
        lse_upd(m2, s2, v2);
        lse_upd(m3, s3, v3);
    }
    lse_mrg(m0, s0, m1, s1);
    lse_mrg(m2, s2, m3, s3);
    lse_mrg(m0, s0, m2, s2);
    g_pm[seg * BN + j] = m0;
    g_ps[seg * BN + j] = s0;
    __threadfence();
    __syncthreads();
    if (tid == 0) lastf = (atomicAdd(&g_cnt[cb], 1u) == SEG - 1);
    __syncthreads();
    if (lastf) {
        __threadfence();
        float M = -INFINITY;
        #pragma unroll
        for (int k = 0; k < SEG; k++) M = fmaxf(M, g_pm[k * BN + j]);
        float S = 0.f;
        #pragma unroll
        for (int k = 0; k < SEG; k++) S += g_ps[k * BN + j] * __expf(g_pm[k * BN + j] - M);
        g_b[j] = -(M + logf(S));
        if (tid == 0) g_cnt[cb] = 0;  // reset for next pass / next graph replay
    }
}

// ---- out[i,:] = y[argmax_j(K~[i,j] + b[j]), :]  (first-max tie-break, like jnp.argmax) ----
__global__ __launch_bounds__(256) void argmax_kernel(const float* __restrict__ Y,
                                                     float* __restrict__ out) {
    __shared__ float sb[BN];   // 32 KB
    __shared__ float rv[256];
    __shared__ int ri[256];
    int tid = threadIdx.x;
    for (int jv = tid; jv < BN / 4; jv += 256)
        ((float4*)sb)[jv] = ((const float4*)g_b)[jv];
    __syncthreads();

    for (int r = 0; r < RPB; r++) {
        int row = blockIdx.x * RPB + r;
        const float* rp = g_K + (size_t)row * BN;
        float best = -INFINITY;
        int bj = 0;
        for (int j = tid; j < BN; j += 256) {
            float v = rp[j] + sb[j];
            if (v > best) { best = v; bj = j; }   // strict > keeps lowest j per thread
        }
        rv[tid] = best; ri[tid] = bj;
        __syncthreads();
        for (int off = 128; off; off >>= 1) {
            if (tid < off) {
                float v2 = rv[tid + off];
                int i2 = ri[tid + off];
                if (v2 > rv[tid] || (v2 == rv[tid] && i2 < ri[tid])) {
                    rv[tid] = v2; ri[tid] = i2;
                }
            }
            __syncthreads();
        }
        int idx = ri[0];
        __syncthreads();
        out[(size_t)row * CD + tid] = Y[(size_t)idx * CD + tid];
    }
}

extern "C" void kernel_launch(void* const* d_in, const int* in_sizes, int n_in,
                              void* d_out, int out_size) {
    const float* x = (const float*)d_in[0];
    const float* y = (const float*)d_in[1];
    // d_in[2] is L (int32, == 100 per problem setup); loop count must be host-side.
    float* out = (float*)d_out;

    init_b_kernel<<<BN / 8, dim3(32, 8)>>>(y);
    gemm_kernel<<<dim3(BN / TB, BN / TB), 256>>>(x, y);
    for (int it = 0; it < LITERS; it++) {
        row_pass_kernel<<<BN / RPB, 256>>>();
        col_pass_kernel<<<dim3(BN / 256, SEG), 256>>>();
    }
    argmax_kernel<<<BN / RPB, 256>>>(y, out);
}

// round 3
// speedup vs baseline: 2.3581x; 2.3581x over previous
#include <cuda_runtime.h>
#include <math.h>

#define BN 8192
#define CD 256
#define LITERS 100
#define SEG 32
#define SEGROWS (BN / SEG)   // 256 rows per segment
#define RPB 8                // rows per block in row-structured kernels
#define TB 128
#define TK 16
#define L2E 1.44269504088896f

// ---- device scratch (no allocations allowed) ----
__device__ float g_K[67108864];          // 8192*8192 fp32 = 256 MB, K~ = 2*x*y^T
__device__ float g_a[BN];
__device__ float g_b[BN];
__device__ float g_pm[SEG * BN];         // partial lse max per (segment, col)
__device__ float g_ps[SEG * BN];         // partial lse sum per (segment, col)
__device__ unsigned int g_cnt[BN / 256]; // per-colblock completion counters (zero-init, self-resetting)

__device__ __forceinline__ float ex2(float x) {
    float y;
    asm("ex2.approx.ftz.f32 %0, %1;" : "=f"(y) : "f"(x));
    return y;
}

// branchless merge of two (max, sum) lse states; difference-based args (exact-ish)
__device__ __forceinline__ void mrg(float& m, float& s, float m2, float s2) {
    float mn = fmaxf(m, m2);
    float e1 = ex2((m - mn) * L2E);
    float e2 = ex2((m2 - mn) * L2E);
    s = fmaf(s, e1, s2 * e2);
    m = mn;
}

// process 8 values into running (m, s): exact online lse, branchless.
// All exp arguments are (v - mn) computed BEFORE scaling by log2(e): the
// subtraction of nearby floats is ~exact, so log-domain error stays ~1e-7
// (the fmaf(v, L2E, ...) form injects ~6e-5 at |v|~300 and flips argmaxes).
__device__ __forceinline__ void lse_chunk8(float& m, float& s,
                                           float v0, float v1, float v2, float v3,
                                           float v4, float v5, float v6, float v7) {
    float cm = fmaxf(fmaxf(fmaxf(v0, v1), fmaxf(v2, v3)),
                     fmaxf(fmaxf(v4, v5), fmaxf(v6, v7)));
    float mn = fmaxf(m, cm);
    float e0 = ex2((v0 - mn) * L2E);
    float e1 = ex2((v1 - mn) * L2E);
    float e2 = ex2((v2 - mn) * L2E);
    float e3 = ex2((v3 - mn) * L2E);
    float e4 = ex2((v4 - mn) * L2E);
    float e5 = ex2((v5 - mn) * L2E);
    float e6 = ex2((v6 - mn) * L2E);
    float e7 = ex2((v7 - mn) * L2E);
    float p = ((e0 + e1) + (e2 + e3)) + ((e4 + e5) + (e6 + e7));
    // correction for previous s; when m == -INF (first chunk): ex2(-INF)=0, s=0 -> p
    s = fmaf(s, ex2((m - mn) * L2E), p);
    m = mn;
}

// ---- b0 = -||y_j||^2 ----
__global__ void init_b_kernel(const float* __restrict__ Y) {
    int row  = blockIdx.x * blockDim.y + threadIdx.y;
    int lane = threadIdx.x;
    const float* yr = Y + (size_t)row * CD;
    float s = 0.f;
    #pragma unroll
    for (int c = lane; c < CD; c += 32) { float v = yr[c]; s += v * v; }
    #pragma unroll
    for (int o = 16; o; o >>= 1) s += __shfl_down_sync(0xffffffffu, s, o);
    if (lane == 0) g_b[row] = -s;
}

// ---- K~ = 2 * X * Y^T  (both row-major [BN, CD], TN gemm) ----
__global__ __launch_bounds__(256) void gemm_kernel(const float* __restrict__ X,
                                                   const float* __restrict__ Y) {
    __shared__ float As[TK][TB + 4];
    __shared__ float Bs[TK][TB + 4];
    int tid = threadIdx.x;
    int i0 = blockIdx.y * TB, j0 = blockIdx.x * TB;
    int tx = tid & 15, ty = tid >> 4;
    int lr = tid >> 2, lk = (tid & 3) << 2;

    float acc[8][8];
    #pragma unroll
    for (int r = 0; r < 8; r++)
        #pragma unroll
        for (int c = 0; c < 8; c++) acc[r][c] = 0.f;

    for (int k0 = 0; k0 < CD; k0 += TK) {
        float4 xa = *(const float4*)(X + (size_t)(i0 + lr) * CD + k0 + lk);
        float4 xb = *(const float4*)(X + (size_t)(i0 + lr + 64) * CD + k0 + lk);
        float4 ya = *(const float4*)(Y + (size_t)(j0 + lr) * CD + k0 + lk);
        float4 yb = *(const float4*)(Y + (size_t)(j0 + lr + 64) * CD + k0 + lk);
        __syncthreads();
        As[lk + 0][lr] = xa.x; As[lk + 1][lr] = xa.y; As[lk + 2][lr] = xa.z; As[lk + 3][lr] = xa.w;
        As[lk + 0][lr + 64] = xb.x; As[lk + 1][lr + 64] = xb.y; As[lk + 2][lr + 64] = xb.z; As[lk + 3][lr + 64] = xb.w;
        Bs[lk + 0][lr] = ya.x; Bs[lk + 1][lr] = ya.y; Bs[lk + 2][lr] = ya.z; Bs[lk + 3][lr] = ya.w;
        Bs[lk + 0][lr + 64] = yb.x; Bs[lk + 1][lr + 64] = yb.y; Bs[lk + 2][lr + 64] = yb.z; Bs[lk + 3][lr + 64] = yb.w;
        __syncthreads();
        #pragma unroll
        for (int kk = 0; kk < TK; kk++) {
            float4 a0 = *(const float4*)&As[kk][ty * 8];
            float4 a1 = *(const float4*)&As[kk][ty * 8 + 4];
            float4 b0 = *(const float4*)&Bs[kk][tx * 8];
            float4 b1 = *(const float4*)&Bs[kk][tx * 8 + 4];
            float ar[8] = {a0.x, a0.y, a0.z, a0.w, a1.x, a1.y, a1.z, a1.w};
            float br[8] = {b0.x, b0.y, b0.z, b0.w, b1.x, b1.y, b1.z, b1.w};
            #pragma unroll
            for (int r = 0; r < 8; r++)
                #pragma unroll
                for (int c = 0; c < 8; c++) acc[r][c] += ar[r] * br[c];
        }
    }
    #pragma unroll
    for (int r = 0; r < 8; r++) {
        float* orow = g_K + (size_t)(i0 + ty * 8 + r) * BN + j0 + tx * 8;
        float4 o0 = make_float4(2.f * acc[r][0], 2.f * acc[r][1], 2.f * acc[r][2], 2.f * acc[r][3]);
        float4 o1 = make_float4(2.f * acc[r][4], 2.f * acc[r][5], 2.f * acc[r][6], 2.f * acc[r][7]);
        *(float4*)orow       = o0;
        *(float4*)(orow + 4) = o1;
    }
}

// ---- a[i] = -lse_j(K~[i,j] + b[j]) : block owns RPB full rows ----
__global__ __launch_bounds__(256) void row_pass_kernel() {
    __shared__ float4 sb4[BN / 4];   // 32 KB: all of b
    __shared__ float wm[8], ws[8];
    int tid = threadIdx.x;
    int lane = tid & 31, wid = tid >> 5;
    const float4* b4 = (const float4*)g_b;
    for (int j = tid; j < BN / 4; j += 256) sb4[j] = b4[j];
    __syncthreads();

    for (int r = 0; r < RPB; r++) {
        int row = blockIdx.x * RPB + r;
        const float4* rp = (const float4*)(g_K + (size_t)row * BN);
        float m = -INFINITY, s = 0.f;
        #pragma unroll
        for (int c = 0; c < 4; c++) {
            int j0 = tid + (2 * c) * 256;
            int j1 = tid + (2 * c + 1) * 256;
            float4 k0 = rp[j0], k1 = rp[j1];
            float4 bb0 = sb4[j0], bb1 = sb4[j1];
            lse_chunk8(m, s,
                       k0.x + bb0.x, k0.y + bb0.y, k0.z + bb0.z, k0.w + bb0.w,
                       k1.x + bb1.x, k1.y + bb1.y, k1.z + bb1.z, k1.w + bb1.w);
        }
        // warp reduce
        #pragma unroll
        for (int off = 16; off; off >>= 1) {
            float m2 = __shfl_down_sync(0xffffffffu, m, off);
            float s2 = __shfl_down_sync(0xffffffffu, s, off);
            mrg(m, s, m2, s2);
        }
        if (lane == 0) { wm[wid] = m; ws[wid] = s; }
        __syncthreads();
        if (wid == 0) {
            float mm = (lane < 8) ? wm[lane] : -INFINITY;
            float ss = (lane < 8) ? ws[lane] : 0.f;
            #pragma unroll
            for (int off = 4; off; off >>= 1) {
                float m2 = __shfl_down_sync(0xffffffffu, mm, off);
                float s2 = __shfl_down_sync(0xffffffffu, ss, off);
                mrg(mm, ss, m2, s2);
            }
            if (lane == 0) g_a[row] = -(mm + logf(ss));
        }
        __syncthreads();
    }
}

// ---- b[j] = -lse_i(K~[i,j] + a[i]) : segmented partials + last-block combine ----
__global__ __launch_bounds__(256) void col_pass_kernel() {
    __shared__ float4 sa4[SEGROWS / 4];
    __shared__ int lastf;
    int cb = blockIdx.x;   // column block 0..31
    int seg = blockIdx.y;  // row segment 0..31
    int tid = threadIdx.x;
    int j = cb * 256 + tid;
    const float4* ga4 = (const float4*)(g_a + seg * SEGROWS);
    if (tid < SEGROWS / 4) sa4[tid] = ga4[tid];
    __syncthreads();

    float m = -INFINITY, s = 0.f;
    const float* p = g_K + (size_t)seg * SEGROWS * BN + j;
    #pragma unroll 4
    for (int c = 0; c < SEGROWS / 8; c++) {
        float4 a0 = sa4[2 * c];
        float4 a1 = sa4[2 * c + 1];
        float k0 = p[0 * BN], k1 = p[1 * BN], k2 = p[2 * BN], k3 = p[3 * BN];
        float k4 = p[4 * BN], k5 = p[5 * BN], k6 = p[6 * BN], k7 = p[7 * BN];
        p += 8 * BN;
        lse_chunk8(m, s,
                   k0 + a0.x, k1 + a0.y, k2 + a0.z, k3 + a0.w,
                   k4 + a1.x, k5 + a1.y, k6 + a1.z, k7 + a1.w);
    }
    g_pm[seg * BN + j] = m;
    g_ps[seg * BN + j] = s;
    __threadfence();
    __syncthreads();
    if (tid == 0) lastf = (atomicAdd(&g_cnt[cb], 1u) == SEG - 1);
    __syncthreads();
    if (lastf) {
        __threadfence();
        float M = -INFINITY;
        #pragma unroll
        for (int k = 0; k < SEG; k++) M = fmaxf(M, g_pm[k * BN + j]);
        float S = 0.f;
        #pragma unroll
        for (int k = 0; k < SEG; k++)
            S = fmaf(g_ps[k * BN + j], ex2((g_pm[k * BN + j] - M) * L2E), S);
        g_b[j] = -(M + logf(S));
        if (tid == 0) g_cnt[cb] = 0;  // reset for next pass / next graph replay
    }
}

// ---- out[i,:] = y[argmax_j(K~[i,j] + b[j]), :]  (first-max tie-break, like jnp.argmax) ----
__global__ __launch_bounds__(256) void argmax_kernel(const float* __restrict__ Y,
                                                     float* __restrict__ out) {
    __shared__ float4 sb4[BN / 4];   // 32 KB
    __shared__ float rv[256];
    __shared__ int ri[256];
    int tid = threadIdx.x;
    const float4* b4 = (const float4*)g_b;
    for (int jv = tid; jv < BN / 4; jv += 256) sb4[jv] = b4[jv];
    __syncthreads();

    for (int r = 0; r < RPB; r++) {
        int row = blockIdx.x * RPB + r;
        const float4* rp = (const float4*)(g_K + (size_t)row * BN);
        float best = -INFINITY;
        int bj = 0;
        #pragma unroll
        for (int it = 0; it < 8; it++) {
            int jj = tid + it * 256;
            float4 k = rp[jj];
            float4 bb = sb4[jj];
            int j = 4 * jj;
            float v0 = k.x + bb.x, v1 = k.y + bb.y, v2 = k.z + bb.z, v3 = k.w + bb.w;
            if (v0 > best) { best = v0; bj = j; }
            if (v1 > best) { best = v1; bj = j + 1; }
            if (v2 > best) { best = v2; bj = j + 2; }
            if (v3 > best) { best = v3; bj = j + 3; }
        }
        rv[tid] = best; ri[tid] = bj;
        __syncthreads();
        for (int off = 128; off; off >>= 1) {
            if (tid < off) {
                float v2 = rv[tid + off];
                int i2 = ri[tid + off];
                if (v2 > rv[tid] || (v2 == rv[tid] && i2 < ri[tid])) {
                    rv[tid] = v2; ri[tid] = i2;
                }
            }
            __syncthreads();
        }
        int idx = ri[0];
        __syncthreads();
        out[(size_t)row * CD + tid] = Y[(size_t)idx * CD + tid];
    }
}

extern "C" void kernel_launch(void* const* d_in, const int* in_sizes, int n_in,
                              void* d_out, int out_size) {
    const float* x = (const float*)d_in[0];
    const float* y = (const float*)d_in[1];
    float* out = (float*)d_out;

    init_b_kernel<<<BN / 8, dim3(32, 8)>>>(y);
    gemm_kernel<<<dim3(BN / TB, BN / TB), 256>>>(x, y);
    for (int it = 0; it < LITERS; it++) {
        row_pass_kernel<<<BN / RPB, 256>>>();
        col_pass_kernel<<<dim3(BN / 256, SEG), 256>>>();
    }
    argmax_kernel<<<BN / RPB, 256>>>(y, out);
}